// round 10
// baseline (speedup 1.0000x reference)
#include <cuda_runtime.h>
#include <cuda_bf16.h>
#include <math.h>

// ---------------- problem-size constants (fixed dataset) ----------------
#define MAXN 50000
#define MAXE 800000
#define MAXET (MAXN + MAXE)
#define MAXB 512

// ---------------- device scratch (static, no allocation) ----------------
__device__ float g_xl[(size_t)MAXN * 128];
__device__ float g_xr[(size_t)MAXN * 128];
__device__ float g_hA[(size_t)MAXN * 128];
__device__ float g_hB[(size_t)MAXN * 128];
__device__ int   g_deg[MAXN];
__device__ int   g_off[MAXN + 1];
__device__ int   g_pos[MAXN];
__device__ int   g_csr[MAXET];              // src ids sorted by dst
__device__ int   g_bsum[64];                // per-block sums for scan

// ---------------- helpers ----------------
__device__ __forceinline__ float warp_sum(float v) {
#pragma unroll
    for (int o = 16; o; o >>= 1) v += __shfl_xor_sync(0xffffffffu, v, o);
    return v;
}

__device__ __forceinline__ unsigned f2tf32(float f) {
    unsigned u;
    asm("cvt.rna.tf32.f32 %0, %1;" : "=r"(u) : "f"(f));
    return u;
}

__device__ __forceinline__ void mma_tf32(float* d, const unsigned* a, const unsigned* b) {
    asm volatile(
        "mma.sync.aligned.m16n8k8.row.col.f32.tf32.tf32.f32 "
        "{%0,%1,%2,%3}, {%4,%5,%6,%7}, {%8,%9}, {%0,%1,%2,%3};"
        : "+f"(d[0]), "+f"(d[1]), "+f"(d[2]), "+f"(d[3])
        : "r"(a[0]), "r"(a[1]), "r"(a[2]), "r"(a[3]), "r"(b[0]), "r"(b[1]));
}

// ---------------- small utility kernels ----------------
__global__ void zero_i(int* p, int n) {
    int i = blockIdx.x * blockDim.x + threadIdx.x;
    if (i < n) p[i] = 0;
}

// edge_index / batch are INT32 (JAX x64 disabled).
// Count in-degrees only (scatter re-reads ei directly; no src/dst staging).
__global__ void prep_edges(const int* __restrict__ ei, int E, int N) {
    int i = blockIdx.x * blockDim.x + threadIdx.x;
    int Etot = E + N;
    if (i >= Etot) return;
    int d = (i < E) ? ei[E + i] : (i - E);
    atomicAdd(&g_deg[d], 1);
}

// ---------------- multi-block scan of g_deg -> g_off ----------------
__global__ void scan_local(int N) {
    __shared__ int wsum[32];
    int b = blockIdx.x, tid = threadIdx.x, lane = tid & 31, wid = tid >> 5;
    int i = b * 1024 + tid;
    int x = (i < N) ? g_deg[i] : 0;
#pragma unroll
    for (int o = 1; o < 32; o <<= 1) {
        int y = __shfl_up_sync(0xffffffffu, x, o);
        if (lane >= o) x += y;
    }
    if (lane == 31) wsum[wid] = x;
    __syncthreads();
    if (wid == 0) {
        int s = wsum[lane];
#pragma unroll
        for (int o = 1; o < 32; o <<= 1) {
            int y = __shfl_up_sync(0xffffffffu, s, o);
            if (lane >= o) s += y;
        }
        wsum[lane] = s;
    }
    __syncthreads();
    int incl = x + (wid ? wsum[wid - 1] : 0);
    if (i < N) g_off[i + 1] = incl;
    if (tid == 1023) g_bsum[b] = incl;
}

__global__ void scan_tops(int nb) {
    __shared__ int s[64];
    int tid = threadIdx.x;
    if (tid < nb) s[tid] = g_bsum[tid];
    __syncthreads();
    if (tid == 0) {
        int a = 0;
        for (int i = 0; i < nb; i++) { int t = s[i]; s[i] = a; a += t; }
    }
    __syncthreads();
    if (tid < nb) g_bsum[tid] = s[tid];
}

__global__ void scan_add(int N) {
    int i = blockIdx.x * blockDim.x + threadIdx.x;
    if (i == 0) g_off[0] = 0;
    if (i < N) {
        g_off[i + 1] += g_bsum[i >> 10];
        g_pos[i] = 0;
    }
}

__global__ void scatter_edges(const int* __restrict__ ei, int E, int N) {
    int i = blockIdx.x * blockDim.x + threadIdx.x;
    int Etot = E + N;
    if (i >= Etot) return;
    int s, d;
    if (i < E) { s = ei[i]; d = ei[E + i]; }
    else       { s = i - E; d = i - E; }
    int p = atomicAdd(&g_pos[d], 1);
    g_csr[g_off[d] + p] = s;
}

// ---------------- tf32 tensor-core dual GEMM ----------------
// {xl,xr}[N,128] = A[N,128] @ {Wl,Wr}[128,128] + bias,  blockIdx.y selects set.
__global__ __launch_bounds__(256, 2) void gemm_tc_dual(
    const float* __restrict__ A,
    const float* __restrict__ W0, const float* __restrict__ b0, float* __restrict__ C0,
    const float* __restrict__ W1, const float* __restrict__ b1, float* __restrict__ C1,
    int N)
{
    const float* W    = blockIdx.y ? W1 : W0;
    const float* bias = blockIdx.y ? b1 : b0;
    float*       C    = blockIdx.y ? C1 : C0;

    __shared__ unsigned A_s[128][36];   // [row][k within 32-chunk], pad 4
    __shared__ unsigned W_s[32][136];   // [k within chunk][col], pad 8

    const int t    = threadIdx.x;
    const int wid  = t >> 5;
    const int lane = t & 31;
    const int gid  = lane >> 2;
    const int tig  = lane & 3;
    const int wm   = wid & 3;
    const int wn   = wid >> 2;
    const int row0 = blockIdx.x * 128;

    float acc[2][8][4];
#pragma unroll
    for (int km = 0; km < 2; km++)
#pragma unroll
        for (int n = 0; n < 8; n++)
#pragma unroll
            for (int c = 0; c < 4; c++) acc[km][n][c] = 0.f;

    for (int kc = 0; kc < 4; kc++) {
#pragma unroll
        for (int i = 0; i < 4; i++) {
            int q = t + i * 256;
            int r = q >> 3, c4 = q & 7;
            float4 a4 = make_float4(0.f, 0.f, 0.f, 0.f);
            if (row0 + r < N)
                a4 = *(const float4*)&A[(size_t)(row0 + r) * 128 + kc * 32 + c4 * 4];
            uint4 ua;
            ua.x = f2tf32(a4.x); ua.y = f2tf32(a4.y);
            ua.z = f2tf32(a4.z); ua.w = f2tf32(a4.w);
            *(uint4*)&A_s[r][c4 * 4] = ua;
            int k = q >> 5, c32 = q & 31;
            float4 w4 = *(const float4*)&W[(size_t)(kc * 32 + k) * 128 + c32 * 4];
            uint4 uw;
            uw.x = f2tf32(w4.x); uw.y = f2tf32(w4.y);
            uw.z = f2tf32(w4.z); uw.w = f2tf32(w4.w);
            *(uint4*)&W_s[k][c32 * 4] = uw;
        }
        __syncthreads();

#pragma unroll
        for (int ks = 0; ks < 4; ks++) {
            const int kq = ks * 8;
            unsigned a[2][4], b[8][2];
#pragma unroll
            for (int km = 0; km < 2; km++) {
                int rb = wm * 32 + km * 16 + gid;
                a[km][0] = A_s[rb    ][kq + tig];
                a[km][1] = A_s[rb + 8][kq + tig];
                a[km][2] = A_s[rb    ][kq + tig + 4];
                a[km][3] = A_s[rb + 8][kq + tig + 4];
            }
#pragma unroll
            for (int n = 0; n < 8; n++) {
                int cb = wn * 64 + n * 8 + gid;
                b[n][0] = W_s[kq + tig    ][cb];
                b[n][1] = W_s[kq + tig + 4][cb];
            }
#pragma unroll
            for (int km = 0; km < 2; km++)
#pragma unroll
                for (int n = 0; n < 8; n++)
                    mma_tf32(acc[km][n], a[km], b[n]);
        }
        __syncthreads();
    }

#pragma unroll
    for (int km = 0; km < 2; km++) {
        int rA = row0 + wm * 32 + km * 16 + gid;
        int rB = rA + 8;
#pragma unroll
        for (int n = 0; n < 8; n++) {
            int col = wn * 64 + n * 8 + 2 * tig;
            float bx = bias[col], by = bias[col + 1];
            if (rA < N) {
                float2 o = make_float2(acc[km][n][0] + bx, acc[km][n][1] + by);
                *(float2*)&C[(size_t)rA * 128 + col] = o;
            }
            if (rB < N) {
                float2 o = make_float2(acc[km][n][2] + bx, acc[km][n][3] + by);
                *(float2*)&C[(size_t)rB * 128 + col] = o;
            }
        }
    }
}

// ---------------- dual small GEMM (M=32) ----------------
__global__ __launch_bounds__(256) void gemm128_dual(
    const float* __restrict__ A,
    const float* __restrict__ W0, const float* __restrict__ b0, float* __restrict__ C0,
    const float* __restrict__ W1, const float* __restrict__ b1, float* __restrict__ C1,
    int N)
{
    const int M = 32;
    const float* W    = blockIdx.y ? W1 : W0;
    const float* bias = blockIdx.y ? b1 : b0;
    float*       C    = blockIdx.y ? C1 : C0;

    __shared__ float As[16][64];
    __shared__ float Ws[16][64];
    const int t = threadIdx.x;
    const int row0 = blockIdx.x * 64;
    const int tx = t & 15, ty = t >> 4;

    float acc[4][4];
#pragma unroll
    for (int i = 0; i < 4; i++)
#pragma unroll
        for (int j = 0; j < 4; j++) acc[i][j] = 0.f;

    for (int k0 = 0; k0 < 128; k0 += 16) {
#pragma unroll
        for (int i = 0; i < 4; i++) {
            int idx = t + i * 256;
            int r = idx >> 4, c = idx & 15;
            int gr = row0 + r;
            As[c][r] = (gr < N) ? A[(size_t)gr * 128 + k0 + c] : 0.f;
        }
#pragma unroll
        for (int i = 0; i < 4; i++) {
            int idx = t + i * 256;
            int kk = idx >> 6, cc = idx & 63;
            Ws[kk][cc] = (cc < M) ? W[(size_t)(k0 + kk) * M + cc] : 0.f;
        }
        __syncthreads();
#pragma unroll
        for (int kk = 0; kk < 16; kk++) {
            float4 a4 = *(const float4*)&As[kk][ty * 4];
            float4 w4 = *(const float4*)&Ws[kk][tx * 4];
            float a[4] = {a4.x, a4.y, a4.z, a4.w};
            float w[4] = {w4.x, w4.y, w4.z, w4.w};
#pragma unroll
            for (int i = 0; i < 4; i++)
#pragma unroll
                for (int j = 0; j < 4; j++) acc[i][j] += a[i] * w[j];
        }
        __syncthreads();
    }
#pragma unroll
    for (int i = 0; i < 4; i++) {
        int r = row0 + ty * 4 + i;
        if (r >= N) continue;
#pragma unroll
        for (int j = 0; j < 4; j++) {
            int c = tx * 4 + j;
            if (c < M) C[(size_t)r * M + c] = acc[i][j] + bias[c];
        }
    }
}

// ---------------- fused GATv2 (H=4), one warp per (node, head) ----------------
// 4x the warp parallelism of warp-per-node: lane = channel within head.
// Each warp reads a disjoint 128B quarter of every src row -> same total
// traffic, 4x outstanding loads chip-wide. Per-head online softmax.
__global__ void gat4_h(const float* __restrict__ xl, const float* __restrict__ xr,
                       const float* __restrict__ att, const float* __restrict__ bias,
                       float* __restrict__ out, int N)
{
    int gw = (blockIdx.x * blockDim.x + threadIdx.x) >> 5;
    if (gw >= N * 4) return;
    int node = gw >> 2;
    int base = (gw & 3) * 32 + (threadIdx.x & 31);   // head*32 + lane

    float xrv  = xr[(size_t)node * 128 + base];
    float attv = att[base];
    float mx = -1e30f, den = 0.f, acc = 0.f;

    const int j0 = g_off[node], j1 = g_off[node + 1];
    int s = g_csr[j0];
    float v = xl[(size_t)s * 128 + base];

    for (int j = j0; j < j1; j++) {
        int jn = (j + 1 < j1) ? j + 1 : j;
        int sn = g_csr[jn];
        float vn = xl[(size_t)sn * 128 + base];       // prefetch next edge

        float t = v + xrv;
        t = fmaxf(t, 0.2f * t);                       // leaky_relu(0.2)
        float p = warp_sum(t * attv);                 // 32-channel head dot

        float nm = fmaxf(mx, p);
        float sc = __expf(mx - nm);                   // first iter: exp(-huge)=0
        float e  = __expf(p - nm);
        mx = nm;
        den = den * sc + e;
        acc = acc * sc + e * v;
        v = vn;
    }

    float o = acc / (den + 1e-16f) + bias[base];
    o = o > 0.f ? o : expm1f(o);                      // ELU
    out[(size_t)node * 128 + base] = o;
}

// ---------------- fused GATv2 (H=1), pair-interleaved ----------------
__global__ void gat1(const float* __restrict__ xl, const float* __restrict__ xr,
                     const float* __restrict__ att, const float* __restrict__ bias,
                     float* __restrict__ out, int N)
{
    int w = (blockIdx.x * blockDim.x + threadIdx.x) >> 5;
    if (w >= N) return;
    int lane = threadIdx.x & 31;

    float xrv  = xr[(size_t)w * 32 + lane];
    float attv = att[lane];
    float mxA = -1e30f, denA = 0.f, accA = 0.f;
    float mxB = -1e30f, denB = 0.f, accB = 0.f;

    const int j0 = g_off[w], j1 = g_off[w + 1];
    int s0 = g_csr[j0];
    int s1 = (j0 + 1 < j1) ? g_csr[j0 + 1] : s0;
    float v0 = xl[(size_t)s0 * 32 + lane];
    float v1 = xl[(size_t)s1 * 32 + lane];

    for (int j = j0; j < j1; j += 2) {
        const bool has1 = (j + 1 < j1);
        int jn = j + 2;
        int sn0 = (jn < j1) ? g_csr[jn] : s0;
        int sn1 = (jn + 1 < j1) ? g_csr[jn + 1] : sn0;
        float vn0 = xl[(size_t)sn0 * 32 + lane];
        float vn1 = xl[(size_t)sn1 * 32 + lane];

        float t0 = v0 + xrv; t0 = fmaxf(t0, 0.2f * t0);
        float t1 = v1 + xrv; t1 = fmaxf(t1, 0.2f * t1);
        float p0 = t0 * attv, p1 = t1 * attv;
#pragma unroll
        for (int o = 16; o; o >>= 1) {
            p0 += __shfl_xor_sync(0xffffffffu, p0, o);
            p1 += __shfl_xor_sync(0xffffffffu, p1, o);
        }

        {
            float nm = fmaxf(mxA, p0);
            float sc = __expf(mxA - nm);
            float e  = __expf(p0 - nm);
            mxA = nm; denA = denA * sc + e; accA = accA * sc + e * v0;
        }
        if (has1) {
            float nm = fmaxf(mxB, p1);
            float sc = __expf(mxB - nm);
            float e  = __expf(p1 - nm);
            mxB = nm; denB = denB * sc + e; accB = accB * sc + e * v1;
        }
        v0 = vn0; v1 = vn1;
    }

    float nm = fmaxf(mxA, mxB);
    float sA = __expf(mxA - nm), sB = __expf(mxB - nm);
    float den = denA * sA + denB * sB;
    float acc = accA * sA + accB * sB;

    float o = acc / (den + 1e-16f) + bias[lane];
    o = o > 0.f ? o : expm1f(o);
    out[(size_t)w * 32 + lane] = o;
}

// ---------------- fused mean-pool + MLP head: one warp per graph ----------------
__global__ void pool_head(const float* __restrict__ h, const int* __restrict__ batch,
                          const float* __restrict__ meta,
                          const float* __restrict__ Wh1, const float* __restrict__ bh1,
                          const float* __restrict__ Wh2, const float* __restrict__ bh2,
                          float* __restrict__ out, int N, int B, int metaDim)
{
    int g = (blockIdx.x * blockDim.x + threadIdx.x) >> 5;
    int lane = threadIdx.x & 31;
    if (g >= B) return;

    int lo = 0, hi = N;
    while (lo < hi) { int m = (lo + hi) >> 1; if (batch[m] < g) lo = m + 1; else hi = m; }
    int start = lo;
    hi = N;
    while (lo < hi) { int m = (lo + hi) >> 1; if (batch[m] < g + 1) lo = m + 1; else hi = m; }
    int end = lo;

    float sum = 0.f;
    int i = start;
    for (; i + 4 <= end; i += 4) {
        float x0 = h[(size_t)(i + 0) * 32 + lane];
        float x1 = h[(size_t)(i + 1) * 32 + lane];
        float x2 = h[(size_t)(i + 2) * 32 + lane];
        float x3 = h[(size_t)(i + 3) * 32 + lane];
        sum += (x0 + x1) + (x2 + x3);
    }
    for (; i < end; i++) sum += h[(size_t)i * 32 + lane];

    float cnt = fmaxf((float)(end - start), 1.f);
    float emb = sum / cnt;

    float acc = bh1[lane];
#pragma unroll
    for (int k = 0; k < 32; k++)
        acc += __shfl_sync(0xffffffffu, emb, k) * Wh1[k * 32 + lane];
    for (int k = 0; k < metaDim; k++)
        acc += meta[(size_t)g * metaDim + k] * Wh1[(32 + k) * 32 + lane];
    acc = fmaxf(acc, 0.f);
    float p = warp_sum(acc * Wh2[lane]);
    if (lane == 0) out[g] = p + bh2[0];
}

// ---------------- host launcher ----------------
extern "C" void kernel_launch(void* const* d_in, const int* in_sizes, int n_in,
                              void* d_out, int out_size)
{
    const float* x     = (const float*)d_in[0];
    const int*   ei    = (const int*)d_in[1];    // int32 (JAX x64 disabled)
    const int*   batch = (const int*)d_in[2];    // int32
    const float* meta  = (const float*)d_in[3];
    const float* Wl[3]  = {(const float*)d_in[4],  (const float*)d_in[10], (const float*)d_in[16]};
    const float* bl[3]  = {(const float*)d_in[5],  (const float*)d_in[11], (const float*)d_in[17]};
    const float* Wr[3]  = {(const float*)d_in[6],  (const float*)d_in[12], (const float*)d_in[18]};
    const float* br[3]  = {(const float*)d_in[7],  (const float*)d_in[13], (const float*)d_in[19]};
    const float* att[3] = {(const float*)d_in[8],  (const float*)d_in[14], (const float*)d_in[20]};
    const float* bc[3]  = {(const float*)d_in[9],  (const float*)d_in[15], (const float*)d_in[21]};
    const float* Wh1 = (const float*)d_in[22];
    const float* bh1 = (const float*)d_in[23];
    const float* Wh2 = (const float*)d_in[24];
    const float* bh2 = (const float*)d_in[25];

    const int N = in_sizes[0] / 128;
    const int E = in_sizes[1] / 2;
    const int metaDim = 12;
    const int B = in_sizes[3] / metaDim;
    const int Etot = E + N;
    const int nb = (N + 1023) / 1024;

    float *xl, *xr, *hA, *hB;
    int *deg;
    cudaGetSymbolAddress((void**)&xl, g_xl);
    cudaGetSymbolAddress((void**)&xr, g_xr);
    cudaGetSymbolAddress((void**)&hA, g_hA);
    cudaGetSymbolAddress((void**)&hB, g_hB);
    cudaGetSymbolAddress((void**)&deg, g_deg);

    const int warpGrid  = (N * 32 + 255) / 256;        // 1 warp / node
    const int warpGrid4 = (N * 4 * 32 + 255) / 256;    // 4 warps / node
    const dim3 bigGrid((N + 127) / 128, 2);
    const dim3 smallGrid((N + 63) / 64, 2);

    // ---- CSR build interleaved with layer-0 GEMM ----
    zero_i<<<(N + 255) / 256, 256>>>(deg, N);
    prep_edges<<<(Etot + 255) / 256, 256>>>(ei, E, N);
    scan_local<<<nb, 1024>>>(N);
    gemm_tc_dual<<<bigGrid, 256>>>(x, Wl[0], bl[0], xl,
                                      Wr[0], br[0], xr, N);
    scan_tops<<<1, 64>>>(nb);
    scan_add<<<(N + 255) / 256, 256>>>(N);       // also zeroes g_pos
    scatter_edges<<<(Etot + 255) / 256, 256>>>(ei, E, N);

    // ---- layer 0 (H=4) ----
    gat4_h<<<warpGrid4, 256>>>(xl, xr, att[0], bc[0], hA, N);

    // ---- layer 1 (H=4) ----
    gemm_tc_dual<<<bigGrid, 256>>>(hA, Wl[1], bl[1], xl,
                                       Wr[1], br[1], xr, N);
    gat4_h<<<warpGrid4, 256>>>(xl, xr, att[1], bc[1], hB, N);

    // ---- layer 2 (H=1) ----
    gemm128_dual<<<smallGrid, 256>>>(hB, Wl[2], bl[2], xl,
                                         Wr[2], br[2], xr, N);
    gat1<<<warpGrid, 256>>>(xl, xr, att[2], bc[2], hA, N);

    // ---- fused mean pool + MLP head ----
    pool_head<<<(B * 32 + 255) / 256, 256>>>(hA, batch, meta, Wh1, bh1, Wh2, bh2,
                                             (float*)d_out, N, B, metaDim);
}

// round 11
// speedup vs baseline: 1.5686x; 1.5686x over previous
#include <cuda_runtime.h>
#include <cuda_bf16.h>
#include <math.h>

// ---------------- problem-size constants (fixed dataset) ----------------
#define MAXN 50000
#define MAXE 800000
#define MAXET (MAXN + MAXE)
#define MAXB 512

// ---------------- device scratch (static, no allocation) ----------------
__device__ float g_xl[(size_t)MAXN * 128];
__device__ float g_xr[(size_t)MAXN * 128];
__device__ float g_hA[(size_t)MAXN * 128];
__device__ float g_hB[(size_t)MAXN * 128];
__device__ int   g_deg[MAXN];
__device__ int   g_off[MAXN + 1];
__device__ int   g_pos[MAXN];
__device__ int   g_csr[MAXET];              // src ids sorted by dst
__device__ int   g_bsum[64];                // per-block sums for scan

// ---------------- f32x2 packed helpers (sm_103a) ----------------
typedef unsigned long long u64;
__device__ __forceinline__ u64 pk2(float x, float y) {
    u64 r; asm("mov.b64 %0, {%1, %2};" : "=l"(r) : "f"(x), "f"(y)); return r;
}
__device__ __forceinline__ void upk2(u64 v, float& x, float& y) {
    asm("mov.b64 {%0, %1}, %2;" : "=f"(x), "=f"(y) : "l"(v));
}
__device__ __forceinline__ u64 ffma2(u64 a, u64 b, u64 c) {
    u64 d; asm("fma.rn.f32x2 %0, %1, %2, %3;" : "=l"(d) : "l"(a), "l"(b), "l"(c)); return d;
}
__device__ __forceinline__ u64 fadd2(u64 a, u64 b) {
    u64 d; asm("add.rn.f32x2 %0, %1, %2;" : "=l"(d) : "l"(a), "l"(b)); return d;
}
__device__ __forceinline__ u64 fmul2(u64 a, u64 b) {
    u64 d; asm("mul.rn.f32x2 %0, %1, %2;" : "=l"(d) : "l"(a), "l"(b)); return d;
}

__device__ __forceinline__ float warp_sum(float v) {
#pragma unroll
    for (int o = 16; o; o >>= 1) v += __shfl_xor_sync(0xffffffffu, v, o);
    return v;
}

__device__ __forceinline__ unsigned f2tf32(float f) {
    unsigned u;
    asm("cvt.rna.tf32.f32 %0, %1;" : "=r"(u) : "f"(f));
    return u;
}

__device__ __forceinline__ void mma_tf32(float* d, const unsigned* a, const unsigned* b) {
    asm volatile(
        "mma.sync.aligned.m16n8k8.row.col.f32.tf32.tf32.f32 "
        "{%0,%1,%2,%3}, {%4,%5,%6,%7}, {%8,%9}, {%0,%1,%2,%3};"
        : "+f"(d[0]), "+f"(d[1]), "+f"(d[2]), "+f"(d[3])
        : "r"(a[0]), "r"(a[1]), "r"(a[2]), "r"(a[3]), "r"(b[0]), "r"(b[1]));
}

// ---------------- small utility kernels ----------------
__global__ void zero_i(int* p, int n) {
    int i = blockIdx.x * blockDim.x + threadIdx.x;
    if (i < n) p[i] = 0;
}

// edge_index / batch are INT32 (JAX x64 disabled).
__global__ void prep_edges(const int* __restrict__ ei, int E, int N) {
    int i = blockIdx.x * blockDim.x + threadIdx.x;
    int Etot = E + N;
    if (i >= Etot) return;
    int d = (i < E) ? ei[E + i] : (i - E);
    atomicAdd(&g_deg[d], 1);
}

// ---------------- multi-block scan of g_deg -> g_off ----------------
__global__ void scan_local(int N) {
    __shared__ int wsum[32];
    int b = blockIdx.x, tid = threadIdx.x, lane = tid & 31, wid = tid >> 5;
    int i = b * 1024 + tid;
    int x = (i < N) ? g_deg[i] : 0;
#pragma unroll
    for (int o = 1; o < 32; o <<= 1) {
        int y = __shfl_up_sync(0xffffffffu, x, o);
        if (lane >= o) x += y;
    }
    if (lane == 31) wsum[wid] = x;
    __syncthreads();
    if (wid == 0) {
        int s = wsum[lane];
#pragma unroll
        for (int o = 1; o < 32; o <<= 1) {
            int y = __shfl_up_sync(0xffffffffu, s, o);
            if (lane >= o) s += y;
        }
        wsum[lane] = s;
    }
    __syncthreads();
    int incl = x + (wid ? wsum[wid - 1] : 0);
    if (i < N) g_off[i + 1] = incl;
    if (tid == 1023) g_bsum[b] = incl;
}

__global__ void scan_tops(int nb) {
    __shared__ int s[64];
    int tid = threadIdx.x;
    if (tid < nb) s[tid] = g_bsum[tid];
    __syncthreads();
    if (tid == 0) {
        int a = 0;
        for (int i = 0; i < nb; i++) { int t = s[i]; s[i] = a; a += t; }
    }
    __syncthreads();
    if (tid < nb) g_bsum[tid] = s[tid];
}

__global__ void scan_add(int N) {
    int i = blockIdx.x * blockDim.x + threadIdx.x;
    if (i == 0) g_off[0] = 0;
    if (i < N) {
        g_off[i + 1] += g_bsum[i >> 10];
        g_pos[i] = 0;
    }
}

__global__ void scatter_edges(const int* __restrict__ ei, int E, int N) {
    int i = blockIdx.x * blockDim.x + threadIdx.x;
    int Etot = E + N;
    if (i >= Etot) return;
    int s, d;
    if (i < E) { s = ei[i]; d = ei[E + i]; }
    else       { s = i - E; d = i - E; }
    int p = atomicAdd(&g_pos[d], 1);
    g_csr[g_off[d] + p] = s;
}

// ---------------- tf32 tensor-core dual GEMM ----------------
__global__ __launch_bounds__(256, 2) void gemm_tc_dual(
    const float* __restrict__ A,
    const float* __restrict__ W0, const float* __restrict__ b0, float* __restrict__ C0,
    const float* __restrict__ W1, const float* __restrict__ b1, float* __restrict__ C1,
    int N)
{
    const float* W    = blockIdx.y ? W1 : W0;
    const float* bias = blockIdx.y ? b1 : b0;
    float*       C    = blockIdx.y ? C1 : C0;

    __shared__ unsigned A_s[128][36];
    __shared__ unsigned W_s[32][136];

    const int t    = threadIdx.x;
    const int wid  = t >> 5;
    const int lane = t & 31;
    const int gid  = lane >> 2;
    const int tig  = lane & 3;
    const int wm   = wid & 3;
    const int wn   = wid >> 2;
    const int row0 = blockIdx.x * 128;

    float acc[2][8][4];
#pragma unroll
    for (int km = 0; km < 2; km++)
#pragma unroll
        for (int n = 0; n < 8; n++)
#pragma unroll
            for (int c = 0; c < 4; c++) acc[km][n][c] = 0.f;

    for (int kc = 0; kc < 4; kc++) {
#pragma unroll
        for (int i = 0; i < 4; i++) {
            int q = t + i * 256;
            int r = q >> 3, c4 = q & 7;
            float4 a4 = make_float4(0.f, 0.f, 0.f, 0.f);
            if (row0 + r < N)
                a4 = *(const float4*)&A[(size_t)(row0 + r) * 128 + kc * 32 + c4 * 4];
            uint4 ua;
            ua.x = f2tf32(a4.x); ua.y = f2tf32(a4.y);
            ua.z = f2tf32(a4.z); ua.w = f2tf32(a4.w);
            *(uint4*)&A_s[r][c4 * 4] = ua;
            int k = q >> 5, c32 = q & 31;
            float4 w4 = *(const float4*)&W[(size_t)(kc * 32 + k) * 128 + c32 * 4];
            uint4 uw;
            uw.x = f2tf32(w4.x); uw.y = f2tf32(w4.y);
            uw.z = f2tf32(w4.z); uw.w = f2tf32(w4.w);
            *(uint4*)&W_s[k][c32 * 4] = uw;
        }
        __syncthreads();

#pragma unroll
        for (int ks = 0; ks < 4; ks++) {
            const int kq = ks * 8;
            unsigned a[2][4], b[8][2];
#pragma unroll
            for (int km = 0; km < 2; km++) {
                int rb = wm * 32 + km * 16 + gid;
                a[km][0] = A_s[rb    ][kq + tig];
                a[km][1] = A_s[rb + 8][kq + tig];
                a[km][2] = A_s[rb    ][kq + tig + 4];
                a[km][3] = A_s[rb + 8][kq + tig + 4];
            }
#pragma unroll
            for (int n = 0; n < 8; n++) {
                int cb = wn * 64 + n * 8 + gid;
                b[n][0] = W_s[kq + tig    ][cb];
                b[n][1] = W_s[kq + tig + 4][cb];
            }
#pragma unroll
            for (int km = 0; km < 2; km++)
#pragma unroll
                for (int n = 0; n < 8; n++)
                    mma_tf32(acc[km][n], a[km], b[n]);
        }
        __syncthreads();
    }

#pragma unroll
    for (int km = 0; km < 2; km++) {
        int rA = row0 + wm * 32 + km * 16 + gid;
        int rB = rA + 8;
#pragma unroll
        for (int n = 0; n < 8; n++) {
            int col = wn * 64 + n * 8 + 2 * tig;
            float bx = bias[col], by = bias[col + 1];
            if (rA < N) {
                float2 o = make_float2(acc[km][n][0] + bx, acc[km][n][1] + by);
                *(float2*)&C[(size_t)rA * 128 + col] = o;
            }
            if (rB < N) {
                float2 o = make_float2(acc[km][n][2] + bx, acc[km][n][3] + by);
                *(float2*)&C[(size_t)rB * 128 + col] = o;
            }
        }
    }
}

// ---------------- dual small GEMM (M=32) ----------------
__global__ __launch_bounds__(256) void gemm128_dual(
    const float* __restrict__ A,
    const float* __restrict__ W0, const float* __restrict__ b0, float* __restrict__ C0,
    const float* __restrict__ W1, const float* __restrict__ b1, float* __restrict__ C1,
    int N)
{
    const int M = 32;
    const float* W    = blockIdx.y ? W1 : W0;
    const float* bias = blockIdx.y ? b1 : b0;
    float*       C    = blockIdx.y ? C1 : C0;

    __shared__ float As[16][64];
    __shared__ float Ws[16][64];
    const int t = threadIdx.x;
    const int row0 = blockIdx.x * 64;
    const int tx = t & 15, ty = t >> 4;

    float acc[4][4];
#pragma unroll
    for (int i = 0; i < 4; i++)
#pragma unroll
        for (int j = 0; j < 4; j++) acc[i][j] = 0.f;

    for (int k0 = 0; k0 < 128; k0 += 16) {
#pragma unroll
        for (int i = 0; i < 4; i++) {
            int idx = t + i * 256;
            int r = idx >> 4, c = idx & 15;
            int gr = row0 + r;
            As[c][r] = (gr < N) ? A[(size_t)gr * 128 + k0 + c] : 0.f;
        }
#pragma unroll
        for (int i = 0; i < 4; i++) {
            int idx = t + i * 256;
            int kk = idx >> 6, cc = idx & 63;
            Ws[kk][cc] = (cc < M) ? W[(size_t)(k0 + kk) * M + cc] : 0.f;
        }
        __syncthreads();
#pragma unroll
        for (int kk = 0; kk < 16; kk++) {
            float4 a4 = *(const float4*)&As[kk][ty * 4];
            float4 w4 = *(const float4*)&Ws[kk][tx * 4];
            float a[4] = {a4.x, a4.y, a4.z, a4.w};
            float w[4] = {w4.x, w4.y, w4.z, w4.w};
#pragma unroll
            for (int i = 0; i < 4; i++)
#pragma unroll
                for (int j = 0; j < 4; j++) acc[i][j] += a[i] * w[j];
        }
        __syncthreads();
    }
#pragma unroll
    for (int i = 0; i < 4; i++) {
        int r = row0 + ty * 4 + i;
        if (r >= N) continue;
#pragma unroll
        for (int j = 0; j < 4; j++) {
            int c = tx * 4 + j;
            if (c < M) C[(size_t)r * M + c] = acc[i][j] + bias[c];
        }
    }
}

// ---------------- fused GATv2 (H=4): warp/node, packed f32x2 hot loop ----------------
// Lane l owns channels [4l..4l+3]; 8-lane group = one head; 3-shfl reduce.
// Online softmax, branchless. Packed fma halves the update instruction count.
__global__ __launch_bounds__(128) void gat4_t(
    const float* __restrict__ xl, const float* __restrict__ xr,
    const float* __restrict__ att, const float* __restrict__ bias,
    float* __restrict__ out, int N)
{
    int w = (blockIdx.x * blockDim.x + threadIdx.x) >> 5;
    if (w >= N) return;
    int lane = threadIdx.x & 31;

    const float4 xrv  = *(const float4*)&xr[(size_t)w * 128 + lane * 4];
    const float4 attv = *(const float4*)&att[lane * 4];
    const u64 xr01 = pk2(xrv.x, xrv.y), xr23 = pk2(xrv.z, xrv.w);
    const u64 at01 = pk2(attv.x, attv.y), at23 = pk2(attv.z, attv.w);
    const u64 c02  = pk2(0.2f, 0.2f);

    float mx = -1e30f, den = 0.f;
    u64 acc01 = pk2(0.f, 0.f), acc23 = pk2(0.f, 0.f);

    const int j0 = g_off[w], j1 = g_off[w + 1];
    int s = g_csr[j0];
    float4 vf = *(const float4*)&xl[(size_t)s * 128 + lane * 4];

    for (int j = j0; j < j1; j++) {
        int jn = (j + 1 < j1) ? j + 1 : j;
        int sn = g_csr[jn];
        float4 vnf = *(const float4*)&xl[(size_t)sn * 128 + lane * 4];  // prefetch

        u64 v01 = pk2(vf.x, vf.y), v23 = pk2(vf.z, vf.w);

        // leaky_relu(v + xr, 0.2): packed add + packed 0.2x, scalar max
        u64 t01 = fadd2(v01, xr01);
        u64 t23 = fadd2(v23, xr23);
        u64 u01 = fmul2(t01, c02);
        u64 u23 = fmul2(t23, c02);
        float ta, tb, tc, td, ua, ub, uc, ud;
        upk2(t01, ta, tb); upk2(t23, tc, td);
        upk2(u01, ua, ub); upk2(u23, uc, ud);
        ta = fmaxf(ta, ua); tb = fmaxf(tb, ub);
        tc = fmaxf(tc, uc); td = fmaxf(td, ud);

        // head dot: packed fma + horizontal 3-shfl reduce
        u64 d2 = fmul2(pk2(ta, tb), at01);
        d2 = ffma2(pk2(tc, td), at23, d2);
        float dl, dh;
        upk2(d2, dl, dh);
        float p = dl + dh;
        p += __shfl_xor_sync(0xffffffffu, p, 1);
        p += __shfl_xor_sync(0xffffffffu, p, 2);
        p += __shfl_xor_sync(0xffffffffu, p, 4);

        // branchless online softmax
        float nm = fmaxf(mx, p);
        float sc = __expf(mx - nm);                // first iter: exp(-huge)=0
        float e  = __expf(p - nm);
        mx = nm;
        den = fmaf(den, sc, e);
        u64 sc2 = pk2(sc, sc), e2 = pk2(e, e);
        acc01 = ffma2(acc01, sc2, fmul2(e2, v01));
        acc23 = ffma2(acc23, sc2, fmul2(e2, v23));
        vf = vnf;
    }

    float inv = 1.f / (den + 1e-16f);
    float4 bv = *(const float4*)&bias[lane * 4];
    float a0, a1, a2, a3;
    upk2(acc01, a0, a1); upk2(acc23, a2, a3);
    float4 o;
    o.x = a0 * inv + bv.x; o.x = o.x > 0.f ? o.x : expm1f(o.x);
    o.y = a1 * inv + bv.y; o.y = o.y > 0.f ? o.y : expm1f(o.y);
    o.z = a2 * inv + bv.z; o.z = o.z > 0.f ? o.z : expm1f(o.z);
    o.w = a3 * inv + bv.w; o.w = o.w > 0.f ? o.w : expm1f(o.w);
    *(float4*)&out[(size_t)w * 128 + lane * 4] = o;
}

// ---------------- fused GATv2 (H=1): warp/node, lane=channel ----------------
__global__ __launch_bounds__(128) void gat1(
    const float* __restrict__ xl, const float* __restrict__ xr,
    const float* __restrict__ att, const float* __restrict__ bias,
    float* __restrict__ out, int N)
{
    int w = (blockIdx.x * blockDim.x + threadIdx.x) >> 5;
    if (w >= N) return;
    int lane = threadIdx.x & 31;

    float xrv  = xr[(size_t)w * 32 + lane];
    float attv = att[lane];
    float mx = -1e30f, den = 0.f, acc = 0.f;

    const int j0 = g_off[w], j1 = g_off[w + 1];
    int s = g_csr[j0];
    float v = xl[(size_t)s * 32 + lane];

    for (int j = j0; j < j1; j++) {
        int jn = (j + 1 < j1) ? j + 1 : j;
        int sn = g_csr[jn];
        float vn = xl[(size_t)sn * 32 + lane];

        float t = v + xrv;
        t = fmaxf(t, 0.2f * t);
        float p = warp_sum(t * attv);

        float nm = fmaxf(mx, p);
        float sc = __expf(mx - nm);
        float e  = __expf(p - nm);
        mx = nm;
        den = fmaf(den, sc, e);
        acc = fmaf(acc, sc, e * v);
        v = vn;
    }

    float o = acc / (den + 1e-16f) + bias[lane];
    o = o > 0.f ? o : expm1f(o);
    out[(size_t)w * 32 + lane] = o;
}

// ---------------- fused mean-pool + MLP head: one warp per graph ----------------
__global__ void pool_head(const float* __restrict__ h, const int* __restrict__ batch,
                          const float* __restrict__ meta,
                          const float* __restrict__ Wh1, const float* __restrict__ bh1,
                          const float* __restrict__ Wh2, const float* __restrict__ bh2,
                          float* __restrict__ out, int N, int B, int metaDim)
{
    int g = (blockIdx.x * blockDim.x + threadIdx.x) >> 5;
    int lane = threadIdx.x & 31;
    if (g >= B) return;

    int lo = 0, hi = N;
    while (lo < hi) { int m = (lo + hi) >> 1; if (batch[m] < g) lo = m + 1; else hi = m; }
    int start = lo;
    hi = N;
    while (lo < hi) { int m = (lo + hi) >> 1; if (batch[m] < g + 1) lo = m + 1; else hi = m; }
    int end = lo;

    float sum = 0.f;
    int i = start;
    for (; i + 4 <= end; i += 4) {
        float x0 = h[(size_t)(i + 0) * 32 + lane];
        float x1 = h[(size_t)(i + 1) * 32 + lane];
        float x2 = h[(size_t)(i + 2) * 32 + lane];
        float x3 = h[(size_t)(i + 3) * 32 + lane];
        sum += (x0 + x1) + (x2 + x3);
    }
    for (; i < end; i++) sum += h[(size_t)i * 32 + lane];

    float cnt = fmaxf((float)(end - start), 1.f);
    float emb = sum / cnt;

    float acc = bh1[lane];
#pragma unroll
    for (int k = 0; k < 32; k++)
        acc += __shfl_sync(0xffffffffu, emb, k) * Wh1[k * 32 + lane];
    for (int k = 0; k < metaDim; k++)
        acc += meta[(size_t)g * metaDim + k] * Wh1[(32 + k) * 32 + lane];
    acc = fmaxf(acc, 0.f);
    float p = warp_sum(acc * Wh2[lane]);
    if (lane == 0) out[g] = p + bh2[0];
}

// ---------------- host launcher ----------------
extern "C" void kernel_launch(void* const* d_in, const int* in_sizes, int n_in,
                              void* d_out, int out_size)
{
    const float* x     = (const float*)d_in[0];
    const int*   ei    = (const int*)d_in[1];    // int32 (JAX x64 disabled)
    const int*   batch = (const int*)d_in[2];    // int32
    const float* meta  = (const float*)d_in[3];
    const float* Wl[3]  = {(const float*)d_in[4],  (const float*)d_in[10], (const float*)d_in[16]};
    const float* bl[3]  = {(const float*)d_in[5],  (const float*)d_in[11], (const float*)d_in[17]};
    const float* Wr[3]  = {(const float*)d_in[6],  (const float*)d_in[12], (const float*)d_in[18]};
    const float* br[3]  = {(const float*)d_in[7],  (const float*)d_in[13], (const float*)d_in[19]};
    const float* att[3] = {(const float*)d_in[8],  (const float*)d_in[14], (const float*)d_in[20]};
    const float* bc[3]  = {(const float*)d_in[9],  (const float*)d_in[15], (const float*)d_in[21]};
    const float* Wh1 = (const float*)d_in[22];
    const float* bh1 = (const float*)d_in[23];
    const float* Wh2 = (const float*)d_in[24];
    const float* bh2 = (const float*)d_in[25];

    const int N = in_sizes[0] / 128;
    const int E = in_sizes[1] / 2;
    const int metaDim = 12;
    const int B = in_sizes[3] / metaDim;
    const int Etot = E + N;
    const int nb = (N + 1023) / 1024;

    float *xl, *xr, *hA, *hB;
    int *deg;
    cudaGetSymbolAddress((void**)&xl, g_xl);
    cudaGetSymbolAddress((void**)&xr, g_xr);
    cudaGetSymbolAddress((void**)&hA, g_hA);
    cudaGetSymbolAddress((void**)&hB, g_hB);
    cudaGetSymbolAddress((void**)&deg, g_deg);

    const int warpGrid = (N * 32 + 127) / 128;     // 1 warp / node, 128-thr blocks
    const dim3 bigGrid((N + 127) / 128, 2);
    const dim3 smallGrid((N + 63) / 64, 2);

    // ---- CSR build interleaved with layer-0 GEMM ----
    zero_i<<<(N + 255) / 256, 256>>>(deg, N);
    prep_edges<<<(Etot + 255) / 256, 256>>>(ei, E, N);
    scan_local<<<nb, 1024>>>(N);
    gemm_tc_dual<<<bigGrid, 256>>>(x, Wl[0], bl[0], xl,
                                      Wr[0], br[0], xr, N);
    scan_tops<<<1, 64>>>(nb);
    scan_add<<<(N + 255) / 256, 256>>>(N);       // also zeroes g_pos
    scatter_edges<<<(Etot + 255) / 256, 256>>>(ei, E, N);

    // ---- layer 0 (H=4) ----
    gat4_t<<<warpGrid, 128>>>(xl, xr, att[0], bc[0], hA, N);

    // ---- layer 1 (H=4) ----
    gemm_tc_dual<<<bigGrid, 256>>>(hA, Wl[1], bl[1], xl,
                                       Wr[1], br[1], xr, N);
    gat4_t<<<warpGrid, 128>>>(xl, xr, att[1], bc[1], hB, N);

    // ---- layer 2 (H=1) ----
    gemm128_dual<<<smallGrid, 256>>>(hB, Wl[2], bl[2], xl,
                                         Wr[2], br[2], xr, N);
    gat1<<<warpGrid, 128>>>(xl, xr, att[2], bc[2], hA, N);

    // ---- fused mean pool + MLP head ----
    pool_head<<<(B * 32 + 255) / 256, 256>>>(hA, batch, meta, Wh1, bh1, Wh2, bh2,
                                             (float*)d_out, N, B, metaDim);
}

// round 12
// speedup vs baseline: 1.5861x; 1.0111x over previous
#include <cuda_runtime.h>
#include <cuda_bf16.h>
#include <math.h>

// ---------------- problem-size constants (fixed dataset) ----------------
#define MAXN 50000
#define MAXE 800000
#define MAXET (MAXN + MAXE)
#define MAXB 512

// GEMM smem layout (in floats): A[2][128][36], W[2][32][136]
#define ABUF 4608          // 128*36
#define WBUF 4352          // 32*136
#define GEMM_SMEM_BYTES ((2*ABUF + 2*WBUF) * 4)   // 71680

// ---------------- device scratch (static, no allocation) ----------------
__device__ float g_xl[(size_t)MAXN * 128];
__device__ float g_xr[(size_t)MAXN * 128];
__device__ float g_hA[(size_t)MAXN * 128];
__device__ float g_hB[(size_t)MAXN * 128];
__device__ int   g_deg[MAXN];
__device__ int   g_off[MAXN + 1];
__device__ int   g_pos[MAXN];
__device__ int   g_csr[MAXET];              // src ids sorted by dst
__device__ int   g_bsum[64];                // per-block sums for scan

// ---------------- f32x2 packed helpers (sm_103a) ----------------
typedef unsigned long long u64;
__device__ __forceinline__ u64 pk2(float x, float y) {
    u64 r; asm("mov.b64 %0, {%1, %2};" : "=l"(r) : "f"(x), "f"(y)); return r;
}
__device__ __forceinline__ void upk2(u64 v, float& x, float& y) {
    asm("mov.b64 {%0, %1}, %2;" : "=f"(x), "=f"(y) : "l"(v));
}
__device__ __forceinline__ u64 ffma2(u64 a, u64 b, u64 c) {
    u64 d; asm("fma.rn.f32x2 %0, %1, %2, %3;" : "=l"(d) : "l"(a), "l"(b), "l"(c)); return d;
}
__device__ __forceinline__ u64 fadd2(u64 a, u64 b) {
    u64 d; asm("add.rn.f32x2 %0, %1, %2;" : "=l"(d) : "l"(a), "l"(b)); return d;
}
__device__ __forceinline__ u64 fmul2(u64 a, u64 b) {
    u64 d; asm("mul.rn.f32x2 %0, %1, %2;" : "=l"(d) : "l"(a), "l"(b)); return d;
}

__device__ __forceinline__ float warp_sum(float v) {
#pragma unroll
    for (int o = 16; o; o >>= 1) v += __shfl_xor_sync(0xffffffffu, v, o);
    return v;
}

__device__ __forceinline__ unsigned f2tf32(float f) {
    unsigned u;
    asm("cvt.rna.tf32.f32 %0, %1;" : "=r"(u) : "f"(f));
    return u;
}

__device__ __forceinline__ void mma_tf32(float* d, const unsigned* a, const unsigned* b) {
    asm volatile(
        "mma.sync.aligned.m16n8k8.row.col.f32.tf32.tf32.f32 "
        "{%0,%1,%2,%3}, {%4,%5,%6,%7}, {%8,%9}, {%0,%1,%2,%3};"
        : "+f"(d[0]), "+f"(d[1]), "+f"(d[2]), "+f"(d[3])
        : "r"(a[0]), "r"(a[1]), "r"(a[2]), "r"(a[3]), "r"(b[0]), "r"(b[1]));
}

__device__ __forceinline__ unsigned smem_u32(const void* p) {
    unsigned a;
    asm("{ .reg .u64 t1; cvta.to.shared.u64 t1, %1; cvt.u32.u64 %0, t1; }"
        : "=r"(a) : "l"(p));
    return a;
}

// ---------------- small utility kernels ----------------
__global__ void zero_i(int* p, int n) {
    int i = blockIdx.x * blockDim.x + threadIdx.x;
    if (i < n) p[i] = 0;
}

// edge_index / batch are INT32 (JAX x64 disabled).
__global__ void prep_edges(const int* __restrict__ ei, int E, int N) {
    int i = blockIdx.x * blockDim.x + threadIdx.x;
    int Etot = E + N;
    if (i >= Etot) return;
    int d = (i < E) ? ei[E + i] : (i - E);
    atomicAdd(&g_deg[d], 1);
}

// ---------------- multi-block scan of g_deg -> g_off ----------------
__global__ void scan_local(int N) {
    __shared__ int wsum[32];
    int b = blockIdx.x, tid = threadIdx.x, lane = tid & 31, wid = tid >> 5;
    int i = b * 1024 + tid;
    int x = (i < N) ? g_deg[i] : 0;
#pragma unroll
    for (int o = 1; o < 32; o <<= 1) {
        int y = __shfl_up_sync(0xffffffffu, x, o);
        if (lane >= o) x += y;
    }
    if (lane == 31) wsum[wid] = x;
    __syncthreads();
    if (wid == 0) {
        int s = wsum[lane];
#pragma unroll
        for (int o = 1; o < 32; o <<= 1) {
            int y = __shfl_up_sync(0xffffffffu, s, o);
            if (lane >= o) s += y;
        }
        wsum[lane] = s;
    }
    __syncthreads();
    int incl = x + (wid ? wsum[wid - 1] : 0);
    if (i < N) g_off[i + 1] = incl;
    if (tid == 1023) g_bsum[b] = incl;
}

__global__ void scan_tops(int nb) {
    __shared__ int s[64];
    int tid = threadIdx.x;
    if (tid < nb) s[tid] = g_bsum[tid];
    __syncthreads();
    if (tid == 0) {
        int a = 0;
        for (int i = 0; i < nb; i++) { int t = s[i]; s[i] = a; a += t; }
    }
    __syncthreads();
    if (tid < nb) g_bsum[tid] = s[tid];
}

__global__ void scan_add(int N) {
    int i = blockIdx.x * blockDim.x + threadIdx.x;
    if (i == 0) g_off[0] = 0;
    if (i < N) {
        g_off[i + 1] += g_bsum[i >> 10];
        g_pos[i] = 0;
    }
}

__global__ void scatter_edges(const int* __restrict__ ei, int E, int N) {
    int i = blockIdx.x * blockDim.x + threadIdx.x;
    int Etot = E + N;
    if (i >= Etot) return;
    int s, d;
    if (i < E) { s = ei[i]; d = ei[E + i]; }
    else       { s = i - E; d = i - E; }
    int p = atomicAdd(&g_pos[d], 1);
    g_csr[g_off[d] + p] = s;
}

// ---------------- tf32 tensor-core dual GEMM, cp.async double-buffered ----------------
// {xl,xr}[N,128] = A[N,128] @ {Wl,Wr}[128,128] + bias,  blockIdx.y selects set.
// Raw f32 staged via cp.async (zero-fill OOB rows); tf32 cvt applied on frag regs.
__global__ __launch_bounds__(256, 2) void gemm_tc_dual(
    const float* __restrict__ A,
    const float* __restrict__ W0, const float* __restrict__ b0, float* __restrict__ C0,
    const float* __restrict__ W1, const float* __restrict__ b1, float* __restrict__ C1,
    int N)
{
    const float* W    = blockIdx.y ? W1 : W0;
    const float* bias = blockIdx.y ? b1 : b0;
    float*       C    = blockIdx.y ? C1 : C0;

    extern __shared__ float sm[];
    float* Abuf = sm;                 // [2][128][36]
    float* Wbuf = sm + 2 * ABUF;      // [2][32][136]
    const unsigned a_base = smem_u32(Abuf);
    const unsigned w_base = smem_u32(Wbuf);

    const int t    = threadIdx.x;
    const int wid  = t >> 5;
    const int lane = t & 31;
    const int gid  = lane >> 2;
    const int tig  = lane & 3;
    const int wm   = wid & 3;
    const int wn   = wid >> 2;
    const int row0 = blockIdx.x * 128;

    float acc[2][8][4];
#pragma unroll
    for (int km = 0; km < 2; km++)
#pragma unroll
        for (int n = 0; n < 8; n++)
#pragma unroll
            for (int c = 0; c < 4; c++) acc[km][n][c] = 0.f;

    // ---- async stage of one K-chunk (kc) into buffer b ----
    auto stage = [&](int kc, int b) {
#pragma unroll
        for (int i = 0; i < 4; i++) {
            int q = t + i * 256;
            // A: 128 rows x 8 float4 per chunk
            int r = q >> 3, c4 = q & 7;
            const float* srcA = A + (size_t)(row0 + r) * 128 + kc * 32 + c4 * 4;
            unsigned dA = a_base + (unsigned)(b * ABUF + r * 36 + c4 * 4) * 4u;
            int szA = (row0 + r < N) ? 16 : 0;
            asm volatile("cp.async.cg.shared.global [%0], [%1], 16, %2;"
                         :: "r"(dA), "l"(srcA), "r"(szA));
            // W: 32 rows x 32 float4 per chunk
            int k = q >> 5, c32 = q & 31;
            const float* srcW = W + (size_t)(kc * 32 + k) * 128 + c32 * 4;
            unsigned dW = w_base + (unsigned)(b * WBUF + k * 136 + c32 * 4) * 4u;
            asm volatile("cp.async.cg.shared.global [%0], [%1], 16;"
                         :: "r"(dW), "l"(srcW));
        }
        asm volatile("cp.async.commit_group;");
    };

    stage(0, 0);                                    // prologue

    for (int kc = 0; kc < 4; kc++) {
        const int b = kc & 1;
        if (kc < 3) {
            stage(kc + 1, b ^ 1);
            asm volatile("cp.async.wait_group 1;");
        } else {
            asm volatile("cp.async.wait_group 0;");
        }
        __syncthreads();

        const float* Ab = Abuf + b * ABUF;
        const float* Wb = Wbuf + b * WBUF;
#pragma unroll
        for (int ks = 0; ks < 4; ks++) {
            const int kq = ks * 8;
            unsigned a[2][4], bb[8][2];
#pragma unroll
            for (int km = 0; km < 2; km++) {
                int rb = wm * 32 + km * 16 + gid;
                a[km][0] = f2tf32(Ab[rb * 36 + kq + tig]);
                a[km][1] = f2tf32(Ab[(rb + 8) * 36 + kq + tig]);
                a[km][2] = f2tf32(Ab[rb * 36 + kq + tig + 4]);
                a[km][3] = f2tf32(Ab[(rb + 8) * 36 + kq + tig + 4]);
            }
#pragma unroll
            for (int n = 0; n < 8; n++) {
                int cb = wn * 64 + n * 8 + gid;
                bb[n][0] = f2tf32(Wb[(kq + tig) * 136 + cb]);
                bb[n][1] = f2tf32(Wb[(kq + tig + 4) * 136 + cb]);
            }
#pragma unroll
            for (int km = 0; km < 2; km++)
#pragma unroll
                for (int n = 0; n < 8; n++)
                    mma_tf32(acc[km][n], a[km], bb[n]);
        }
        __syncthreads();                            // protect buffer reuse
    }

    // ---- epilogue: add bias, store ----
#pragma unroll
    for (int km = 0; km < 2; km++) {
        int rA = row0 + wm * 32 + km * 16 + gid;
        int rB = rA + 8;
#pragma unroll
        for (int n = 0; n < 8; n++) {
            int col = wn * 64 + n * 8 + 2 * tig;
            float bx = bias[col], by = bias[col + 1];
            if (rA < N) {
                float2 o = make_float2(acc[km][n][0] + bx, acc[km][n][1] + by);
                *(float2*)&C[(size_t)rA * 128 + col] = o;
            }
            if (rB < N) {
                float2 o = make_float2(acc[km][n][2] + bx, acc[km][n][3] + by);
                *(float2*)&C[(size_t)rB * 128 + col] = o;
            }
        }
    }
}

// ---------------- dual small GEMM (M=32) ----------------
__global__ __launch_bounds__(256) void gemm128_dual(
    const float* __restrict__ A,
    const float* __restrict__ W0, const float* __restrict__ b0, float* __restrict__ C0,
    const float* __restrict__ W1, const float* __restrict__ b1, float* __restrict__ C1,
    int N)
{
    const int M = 32;
    const float* W    = blockIdx.y ? W1 : W0;
    const float* bias = blockIdx.y ? b1 : b0;
    float*       C    = blockIdx.y ? C1 : C0;

    __shared__ float As[16][64];
    __shared__ float Ws[16][64];
    const int t = threadIdx.x;
    const int row0 = blockIdx.x * 64;
    const int tx = t & 15, ty = t >> 4;

    float acc[4][4];
#pragma unroll
    for (int i = 0; i < 4; i++)
#pragma unroll
        for (int j = 0; j < 4; j++) acc[i][j] = 0.f;

    for (int k0 = 0; k0 < 128; k0 += 16) {
#pragma unroll
        for (int i = 0; i < 4; i++) {
            int idx = t + i * 256;
            int r = idx >> 4, c = idx & 15;
            int gr = row0 + r;
            As[c][r] = (gr < N) ? A[(size_t)gr * 128 + k0 + c] : 0.f;
        }
#pragma unroll
        for (int i = 0; i < 4; i++) {
            int idx = t + i * 256;
            int kk = idx >> 6, cc = idx & 63;
            Ws[kk][cc] = (cc < M) ? W[(size_t)(k0 + kk) * M + cc] : 0.f;
        }
        __syncthreads();
#pragma unroll
        for (int kk = 0; kk < 16; kk++) {
            float4 a4 = *(const float4*)&As[kk][ty * 4];
            float4 w4 = *(const float4*)&Ws[kk][tx * 4];
            float a[4] = {a4.x, a4.y, a4.z, a4.w};
            float w[4] = {w4.x, w4.y, w4.z, w4.w};
#pragma unroll
            for (int i = 0; i < 4; i++)
#pragma unroll
                for (int j = 0; j < 4; j++) acc[i][j] += a[i] * w[j];
        }
        __syncthreads();
    }
#pragma unroll
    for (int i = 0; i < 4; i++) {
        int r = row0 + ty * 4 + i;
        if (r >= N) continue;
#pragma unroll
        for (int j = 0; j < 4; j++) {
            int c = tx * 4 + j;
            if (c < M) C[(size_t)r * M + c] = acc[i][j] + bias[c];
        }
    }
}

// ---------------- fused GATv2 (H=4): warp/node, packed f32x2 hot loop ----------------
__global__ __launch_bounds__(128) void gat4_t(
    const float* __restrict__ xl, const float* __restrict__ xr,
    const float* __restrict__ att, const float* __restrict__ bias,
    float* __restrict__ out, int N)
{
    int w = (blockIdx.x * blockDim.x + threadIdx.x) >> 5;
    if (w >= N) return;
    int lane = threadIdx.x & 31;

    const float4 xrv  = *(const float4*)&xr[(size_t)w * 128 + lane * 4];
    const float4 attv = *(const float4*)&att[lane * 4];
    const u64 xr01 = pk2(xrv.x, xrv.y), xr23 = pk2(xrv.z, xrv.w);
    const u64 at01 = pk2(attv.x, attv.y), at23 = pk2(attv.z, attv.w);
    const u64 c02  = pk2(0.2f, 0.2f);

    float mx = -1e30f, den = 0.f;
    u64 acc01 = pk2(0.f, 0.f), acc23 = pk2(0.f, 0.f);

    const int j0 = g_off[w], j1 = g_off[w + 1];
    int s = g_csr[j0];
    float4 vf = *(const float4*)&xl[(size_t)s * 128 + lane * 4];

    for (int j = j0; j < j1; j++) {
        int jn = (j + 1 < j1) ? j + 1 : j;
        int sn = g_csr[jn];
        float4 vnf = *(const float4*)&xl[(size_t)sn * 128 + lane * 4];  // prefetch

        u64 v01 = pk2(vf.x, vf.y), v23 = pk2(vf.z, vf.w);

        u64 t01 = fadd2(v01, xr01);
        u64 t23 = fadd2(v23, xr23);
        u64 u01 = fmul2(t01, c02);
        u64 u23 = fmul2(t23, c02);
        float ta, tb, tc, td, ua, ub, uc, ud;
        upk2(t01, ta, tb); upk2(t23, tc, td);
        upk2(u01, ua, ub); upk2(u23, uc, ud);
        ta = fmaxf(ta, ua); tb = fmaxf(tb, ub);
        tc = fmaxf(tc, uc); td = fmaxf(td, ud);

        u64 d2 = fmul2(pk2(ta, tb), at01);
        d2 = ffma2(pk2(tc, td), at23, d2);
        float dl, dh;
        upk2(d2, dl, dh);
        float p = dl + dh;
        p += __shfl_xor_sync(0xffffffffu, p, 1);
        p += __shfl_xor_sync(0xffffffffu, p, 2);
        p += __shfl_xor_sync(0xffffffffu, p, 4);

        float nm = fmaxf(mx, p);
        float sc = __expf(mx - nm);
        float e  = __expf(p - nm);
        mx = nm;
        den = fmaf(den, sc, e);
        u64 sc2 = pk2(sc, sc), e2 = pk2(e, e);
        acc01 = ffma2(acc01, sc2, fmul2(e2, v01));
        acc23 = ffma2(acc23, sc2, fmul2(e2, v23));
        vf = vnf;
    }

    float inv = 1.f / (den + 1e-16f);
    float4 bv = *(const float4*)&bias[lane * 4];
    float a0, a1, a2, a3;
    upk2(acc01, a0, a1); upk2(acc23, a2, a3);
    float4 o;
    o.x = a0 * inv + bv.x; o.x = o.x > 0.f ? o.x : expm1f(o.x);
    o.y = a1 * inv + bv.y; o.y = o.y > 0.f ? o.y : expm1f(o.y);
    o.z = a2 * inv + bv.z; o.z = o.z > 0.f ? o.z : expm1f(o.z);
    o.w = a3 * inv + bv.w; o.w = o.w > 0.f ? o.w : expm1f(o.w);
    *(float4*)&out[(size_t)w * 128 + lane * 4] = o;
}

// ---------------- fused GATv2 (H=1): warp/node, lane=channel ----------------
__global__ __launch_bounds__(128) void gat1(
    const float* __restrict__ xl, const float* __restrict__ xr,
    const float* __restrict__ att, const float* __restrict__ bias,
    float* __restrict__ out, int N)
{
    int w = (blockIdx.x * blockDim.x + threadIdx.x) >> 5;
    if (w >= N) return;
    int lane = threadIdx.x & 31;

    float xrv  = xr[(size_t)w * 32 + lane];
    float attv = att[lane];
    float mx = -1e30f, den = 0.f, acc = 0.f;

    const int j0 = g_off[w], j1 = g_off[w + 1];
    int s = g_csr[j0];
    float v = xl[(size_t)s * 32 + lane];

    for (int j = j0; j < j1; j++) {
        int jn = (j + 1 < j1) ? j + 1 : j;
        int sn = g_csr[jn];
        float vn = xl[(size_t)sn * 32 + lane];

        float t = v + xrv;
        t = fmaxf(t, 0.2f * t);
        float p = warp_sum(t * attv);

        float nm = fmaxf(mx, p);
        float sc = __expf(mx - nm);
        float e  = __expf(p - nm);
        mx = nm;
        den = fmaf(den, sc, e);
        acc = fmaf(acc, sc, e * v);
        v = vn;
    }

    float o = acc / (den + 1e-16f) + bias[lane];
    o = o > 0.f ? o : expm1f(o);
    out[(size_t)w * 32 + lane] = o;
}

// ---------------- fused mean-pool + MLP head: one warp per graph ----------------
__global__ void pool_head(const float* __restrict__ h, const int* __restrict__ batch,
                          const float* __restrict__ meta,
                          const float* __restrict__ Wh1, const float* __restrict__ bh1,
                          const float* __restrict__ Wh2, const float* __restrict__ bh2,
                          float* __restrict__ out, int N, int B, int metaDim)
{
    int g = (blockIdx.x * blockDim.x + threadIdx.x) >> 5;
    int lane = threadIdx.x & 31;
    if (g >= B) return;

    int lo = 0, hi = N;
    while (lo < hi) { int m = (lo + hi) >> 1; if (batch[m] < g) lo = m + 1; else hi = m; }
    int start = lo;
    hi = N;
    while (lo < hi) { int m = (lo + hi) >> 1; if (batch[m] < g + 1) lo = m + 1; else hi = m; }
    int end = lo;

    float sum = 0.f;
    int i = start;
    for (; i + 4 <= end; i += 4) {
        float x0 = h[(size_t)(i + 0) * 32 + lane];
        float x1 = h[(size_t)(i + 1) * 32 + lane];
        float x2 = h[(size_t)(i + 2) * 32 + lane];
        float x3 = h[(size_t)(i + 3) * 32 + lane];
        sum += (x0 + x1) + (x2 + x3);
    }
    for (; i < end; i++) sum += h[(size_t)i * 32 + lane];

    float cnt = fmaxf((float)(end - start), 1.f);
    float emb = sum / cnt;

    float acc = bh1[lane];
#pragma unroll
    for (int k = 0; k < 32; k++)
        acc += __shfl_sync(0xffffffffu, emb, k) * Wh1[k * 32 + lane];
    for (int k = 0; k < metaDim; k++)
        acc += meta[(size_t)g * metaDim + k] * Wh1[(32 + k) * 32 + lane];
    acc = fmaxf(acc, 0.f);
    float p = warp_sum(acc * Wh2[lane]);
    if (lane == 0) out[g] = p + bh2[0];
}

// ---------------- host launcher ----------------
extern "C" void kernel_launch(void* const* d_in, const int* in_sizes, int n_in,
                              void* d_out, int out_size)
{
    const float* x     = (const float*)d_in[0];
    const int*   ei    = (const int*)d_in[1];    // int32 (JAX x64 disabled)
    const int*   batch = (const int*)d_in[2];    // int32
    const float* meta  = (const float*)d_in[3];
    const float* Wl[3]  = {(const float*)d_in[4],  (const float*)d_in[10], (const float*)d_in[16]};
    const float* bl[3]  = {(const float*)d_in[5],  (const float*)d_in[11], (const float*)d_in[17]};
    const float* Wr[3]  = {(const float*)d_in[6],  (const float*)d_in[12], (const float*)d_in[18]};
    const float* br[3]  = {(const float*)d_in[7],  (const float*)d_in[13], (const float*)d_in[19]};
    const float* att[3] = {(const float*)d_in[8],  (const float*)d_in[14], (const float*)d_in[20]};
    const float* bc[3]  = {(const float*)d_in[9],  (const float*)d_in[15], (const float*)d_in[21]};
    const float* Wh1 = (const float*)d_in[22];
    const float* bh1 = (const float*)d_in[23];
    const float* Wh2 = (const float*)d_in[24];
    const float* bh2 = (const float*)d_in[25];

    const int N = in_sizes[0] / 128;
    const int E = in_sizes[1] / 2;
    const int metaDim = 12;
    const int B = in_sizes[3] / metaDim;
    const int Etot = E + N;
    const int nb = (N + 1023) / 1024;

    float *xl, *xr, *hA, *hB;
    int *deg;
    cudaGetSymbolAddress((void**)&xl, g_xl);
    cudaGetSymbolAddress((void**)&xr, g_xr);
    cudaGetSymbolAddress((void**)&hA, g_hA);
    cudaGetSymbolAddress((void**)&hB, g_hB);
    cudaGetSymbolAddress((void**)&deg, g_deg);

    static int smem_set = 0;
    if (!smem_set) {
        cudaFuncSetAttribute(gemm_tc_dual,
                             cudaFuncAttributeMaxDynamicSharedMemorySize,
                             GEMM_SMEM_BYTES);
        smem_set = 1;
    }

    const int warpGrid = (N * 32 + 127) / 128;     // 1 warp / node, 128-thr blocks
    const dim3 bigGrid((N + 127) / 128, 2);
    const dim3 smallGrid((N + 63) / 64, 2);

    // ---- CSR build interleaved with layer-0 GEMM ----
    zero_i<<<(N + 255) / 256, 256>>>(deg, N);
    prep_edges<<<(Etot + 255) / 256, 256>>>(ei, E, N);
    scan_local<<<nb, 1024>>>(N);
    gemm_tc_dual<<<bigGrid, 256, GEMM_SMEM_BYTES>>>(x, Wl[0], bl[0], xl,
                                                       Wr[0], br[0], xr, N);
    scan_tops<<<1, 64>>>(nb);
    scan_add<<<(N + 255) / 256, 256>>>(N);       // also zeroes g_pos
    scatter_edges<<<(Etot + 255) / 256, 256>>>(ei, E, N);

    // ---- layer 0 (H=4) ----
    gat4_t<<<warpGrid, 128>>>(xl, xr, att[0], bc[0], hA, N);

    // ---- layer 1 (H=4) ----
    gemm_tc_dual<<<bigGrid, 256, GEMM_SMEM_BYTES>>>(hA, Wl[1], bl[1], xl,
                                                        Wr[1], br[1], xr, N);
    gat4_t<<<warpGrid, 128>>>(xl, xr, att[1], bc[1], hB, N);

    // ---- layer 2 (H=1) ----
    gemm128_dual<<<smallGrid, 256>>>(hB, Wl[2], bl[2], xl,
                                         Wr[2], br[2], xr, N);
    gat1<<<warpGrid, 128>>>(xl, xr, att[2], bc[2], hA, N);

    // ---- fused mean pool + MLP head ----
    pool_head<<<(B * 32 + 255) / 256, 256>>>(hA, batch, meta, Wh1, bh1, Wh2, bh2,
                                             (float*)d_out, N, B, metaDim);
}

// round 13
// speedup vs baseline: 1.5952x; 1.0057x over previous
#include <cuda_runtime.h>
#include <cuda_fp16.h>
#include <cuda_bf16.h>
#include <math.h>

// ---------------- problem-size constants (fixed dataset) ----------------
#define MAXN 50000
#define MAXE 800000
#define MAXET (MAXN + MAXE)
#define MAXB 512

// GEMM smem layout (in floats): A[2][128][36], W[2][32][136]
#define ABUF 4608          // 128*36
#define WBUF 4352          // 32*136
#define GEMM_SMEM_BYTES ((2*ABUF + 2*WBUF) * 4)   // 71680

// ---------------- device scratch (static, no allocation) ----------------
__device__ float  g_xl[(size_t)MAXN * 128];
__device__ __half g_xlh[(size_t)MAXN * 128];   // fp16 mirror of xl (gather path)
__device__ float  g_xr[(size_t)MAXN * 128];
__device__ float  g_hA[(size_t)MAXN * 128];
__device__ float  g_hB[(size_t)MAXN * 128];
__device__ int    g_deg[MAXN];
__device__ int    g_off[MAXN + 1];
__device__ int    g_pos[MAXN];
__device__ int    g_csr[MAXET];              // src ids sorted by dst
__device__ int    g_bsum[64];                // per-block sums for scan

// ---------------- f32x2 packed helpers (sm_103a) ----------------
typedef unsigned long long u64;
__device__ __forceinline__ u64 pk2(float x, float y) {
    u64 r; asm("mov.b64 %0, {%1, %2};" : "=l"(r) : "f"(x), "f"(y)); return r;
}
__device__ __forceinline__ void upk2(u64 v, float& x, float& y) {
    asm("mov.b64 {%0, %1}, %2;" : "=f"(x), "=f"(y) : "l"(v));
}
__device__ __forceinline__ u64 ffma2(u64 a, u64 b, u64 c) {
    u64 d; asm("fma.rn.f32x2 %0, %1, %2, %3;" : "=l"(d) : "l"(a), "l"(b), "l"(c)); return d;
}
__device__ __forceinline__ u64 fadd2(u64 a, u64 b) {
    u64 d; asm("add.rn.f32x2 %0, %1, %2;" : "=l"(d) : "l"(a), "l"(b)); return d;
}
__device__ __forceinline__ u64 fmul2(u64 a, u64 b) {
    u64 d; asm("mul.rn.f32x2 %0, %1, %2;" : "=l"(d) : "l"(a), "l"(b)); return d;
}

__device__ __forceinline__ float warp_sum(float v) {
#pragma unroll
    for (int o = 16; o; o >>= 1) v += __shfl_xor_sync(0xffffffffu, v, o);
    return v;
}

__device__ __forceinline__ unsigned f2tf32(float f) {
    unsigned u;
    asm("cvt.rna.tf32.f32 %0, %1;" : "=r"(u) : "f"(f));
    return u;
}

__device__ __forceinline__ void mma_tf32(float* d, const unsigned* a, const unsigned* b) {
    asm volatile(
        "mma.sync.aligned.m16n8k8.row.col.f32.tf32.tf32.f32 "
        "{%0,%1,%2,%3}, {%4,%5,%6,%7}, {%8,%9}, {%0,%1,%2,%3};"
        : "+f"(d[0]), "+f"(d[1]), "+f"(d[2]), "+f"(d[3])
        : "r"(a[0]), "r"(a[1]), "r"(a[2]), "r"(a[3]), "r"(b[0]), "r"(b[1]));
}

__device__ __forceinline__ unsigned smem_u32(const void* p) {
    unsigned a;
    asm("{ .reg .u64 t1; cvta.to.shared.u64 t1, %1; cvt.u32.u64 %0, t1; }"
        : "=r"(a) : "l"(p));
    return a;
}

// ---------------- small utility kernels ----------------
__global__ void zero_i(int* p, int n) {
    int i = blockIdx.x * blockDim.x + threadIdx.x;
    if (i < n) p[i] = 0;
}

// edge_index / batch are INT32 (JAX x64 disabled).
__global__ void prep_edges(const int* __restrict__ ei, int E, int N) {
    int i = blockIdx.x * blockDim.x + threadIdx.x;
    int Etot = E + N;
    if (i >= Etot) return;
    int d = (i < E) ? ei[E + i] : (i - E);
    atomicAdd(&g_deg[d], 1);
}

// ---------------- multi-block scan of g_deg -> g_off ----------------
__global__ void scan_local(int N) {
    __shared__ int wsum[32];
    int b = blockIdx.x, tid = threadIdx.x, lane = tid & 31, wid = tid >> 5;
    int i = b * 1024 + tid;
    int x = (i < N) ? g_deg[i] : 0;
#pragma unroll
    for (int o = 1; o < 32; o <<= 1) {
        int y = __shfl_up_sync(0xffffffffu, x, o);
        if (lane >= o) x += y;
    }
    if (lane == 31) wsum[wid] = x;
    __syncthreads();
    if (wid == 0) {
        int s = wsum[lane];
#pragma unroll
        for (int o = 1; o < 32; o <<= 1) {
            int y = __shfl_up_sync(0xffffffffu, s, o);
            if (lane >= o) s += y;
        }
        wsum[lane] = s;
    }
    __syncthreads();
    int incl = x + (wid ? wsum[wid - 1] : 0);
    if (i < N) g_off[i + 1] = incl;
    if (tid == 1023) g_bsum[b] = incl;
}

__global__ void scan_tops(int nb) {
    __shared__ int s[64];
    int tid = threadIdx.x;
    if (tid < nb) s[tid] = g_bsum[tid];
    __syncthreads();
    if (tid == 0) {
        int a = 0;
        for (int i = 0; i < nb; i++) { int t = s[i]; s[i] = a; a += t; }
    }
    __syncthreads();
    if (tid < nb) g_bsum[tid] = s[tid];
}

__global__ void scan_add(int N) {
    int i = blockIdx.x * blockDim.x + threadIdx.x;
    if (i == 0) g_off[0] = 0;
    if (i < N) {
        g_off[i + 1] += g_bsum[i >> 10];
        g_pos[i] = 0;
    }
}

__global__ void scatter_edges(const int* __restrict__ ei, int E, int N) {
    int i = blockIdx.x * blockDim.x + threadIdx.x;
    int Etot = E + N;
    if (i >= Etot) return;
    int s, d;
    if (i < E) { s = ei[i]; d = ei[E + i]; }
    else       { s = i - E; d = i - E; }
    int p = atomicAdd(&g_pos[d], 1);
    g_csr[g_off[d] + p] = s;
}

// ---------------- tf32 tensor-core dual GEMM, cp.async double-buffered ----------------
// {xl,xr}[N,128] = A[N,128] @ {Wl,Wr}[128,128] + bias,  blockIdx.y selects set.
// blockIdx.y==0 additionally writes fp16 mirror H0 of xl for the gather path.
__global__ __launch_bounds__(256, 2) void gemm_tc_dual(
    const float* __restrict__ A,
    const float* __restrict__ W0, const float* __restrict__ b0, float* __restrict__ C0,
    const float* __restrict__ W1, const float* __restrict__ b1, float* __restrict__ C1,
    __half* __restrict__ H0, int N)
{
    const float* W    = blockIdx.y ? W1 : W0;
    const float* bias = blockIdx.y ? b1 : b0;
    float*       C    = blockIdx.y ? C1 : C0;

    extern __shared__ float sm[];
    float* Abuf = sm;                 // [2][128][36]
    float* Wbuf = sm + 2 * ABUF;      // [2][32][136]
    const unsigned a_base = smem_u32(Abuf);
    const unsigned w_base = smem_u32(Wbuf);

    const int t    = threadIdx.x;
    const int wid  = t >> 5;
    const int lane = t & 31;
    const int gid  = lane >> 2;
    const int tig  = lane & 3;
    const int wm   = wid & 3;
    const int wn   = wid >> 2;
    const int row0 = blockIdx.x * 128;

    float acc[2][8][4];
#pragma unroll
    for (int km = 0; km < 2; km++)
#pragma unroll
        for (int n = 0; n < 8; n++)
#pragma unroll
            for (int c = 0; c < 4; c++) acc[km][n][c] = 0.f;

    auto stage = [&](int kc, int b) {
#pragma unroll
        for (int i = 0; i < 4; i++) {
            int q = t + i * 256;
            int r = q >> 3, c4 = q & 7;
            const float* srcA = A + (size_t)(row0 + r) * 128 + kc * 32 + c4 * 4;
            unsigned dA = a_base + (unsigned)(b * ABUF + r * 36 + c4 * 4) * 4u;
            int szA = (row0 + r < N) ? 16 : 0;
            asm volatile("cp.async.cg.shared.global [%0], [%1], 16, %2;"
                         :: "r"(dA), "l"(srcA), "r"(szA));
            int k = q >> 5, c32 = q & 31;
            const float* srcW = W + (size_t)(kc * 32 + k) * 128 + c32 * 4;
            unsigned dW = w_base + (unsigned)(b * WBUF + k * 136 + c32 * 4) * 4u;
            asm volatile("cp.async.cg.shared.global [%0], [%1], 16;"
                         :: "r"(dW), "l"(srcW));
        }
        asm volatile("cp.async.commit_group;");
    };

    stage(0, 0);

    for (int kc = 0; kc < 4; kc++) {
        const int b = kc & 1;
        if (kc < 3) {
            stage(kc + 1, b ^ 1);
            asm volatile("cp.async.wait_group 1;");
        } else {
            asm volatile("cp.async.wait_group 0;");
        }
        __syncthreads();

        const float* Ab = Abuf + b * ABUF;
        const float* Wb = Wbuf + b * WBUF;
#pragma unroll
        for (int ks = 0; ks < 4; ks++) {
            const int kq = ks * 8;
            unsigned a[2][4], bb[8][2];
#pragma unroll
            for (int km = 0; km < 2; km++) {
                int rb = wm * 32 + km * 16 + gid;
                a[km][0] = f2tf32(Ab[rb * 36 + kq + tig]);
                a[km][1] = f2tf32(Ab[(rb + 8) * 36 + kq + tig]);
                a[km][2] = f2tf32(Ab[rb * 36 + kq + tig + 4]);
                a[km][3] = f2tf32(Ab[(rb + 8) * 36 + kq + tig + 4]);
            }
#pragma unroll
            for (int n = 0; n < 8; n++) {
                int cb = wn * 64 + n * 8 + gid;
                bb[n][0] = f2tf32(Wb[(kq + tig) * 136 + cb]);
                bb[n][1] = f2tf32(Wb[(kq + tig + 4) * 136 + cb]);
            }
#pragma unroll
            for (int km = 0; km < 2; km++)
#pragma unroll
                for (int n = 0; n < 8; n++)
                    mma_tf32(acc[km][n], a[km], bb[n]);
        }
        __syncthreads();
    }

    const bool isXl = (blockIdx.y == 0);
#pragma unroll
    for (int km = 0; km < 2; km++) {
        int rA = row0 + wm * 32 + km * 16 + gid;
        int rB = rA + 8;
#pragma unroll
        for (int n = 0; n < 8; n++) {
            int col = wn * 64 + n * 8 + 2 * tig;
            float bx = bias[col], by = bias[col + 1];
            if (rA < N) {
                float ox = acc[km][n][0] + bx, oy = acc[km][n][1] + by;
                *(float2*)&C[(size_t)rA * 128 + col] = make_float2(ox, oy);
                if (isXl)
                    *(__half2*)&H0[(size_t)rA * 128 + col] = __floats2half2_rn(ox, oy);
            }
            if (rB < N) {
                float ox = acc[km][n][2] + bx, oy = acc[km][n][3] + by;
                *(float2*)&C[(size_t)rB * 128 + col] = make_float2(ox, oy);
                if (isXl)
                    *(__half2*)&H0[(size_t)rB * 128 + col] = __floats2half2_rn(ox, oy);
            }
        }
    }
}

// ---------------- dual small GEMM (M=32); y==0 also writes fp16 mirror ----------------
__global__ __launch_bounds__(256) void gemm128_dual(
    const float* __restrict__ A,
    const float* __restrict__ W0, const float* __restrict__ b0, float* __restrict__ C0,
    const float* __restrict__ W1, const float* __restrict__ b1, float* __restrict__ C1,
    __half* __restrict__ H0, int N)
{
    const int M = 32;
    const float* W    = blockIdx.y ? W1 : W0;
    const float* bias = blockIdx.y ? b1 : b0;
    float*       C    = blockIdx.y ? C1 : C0;
    const bool isXl = (blockIdx.y == 0);

    __shared__ float As[16][64];
    __shared__ float Ws[16][64];
    const int t = threadIdx.x;
    const int row0 = blockIdx.x * 64;
    const int tx = t & 15, ty = t >> 4;

    float acc[4][4];
#pragma unroll
    for (int i = 0; i < 4; i++)
#pragma unroll
        for (int j = 0; j < 4; j++) acc[i][j] = 0.f;

    for (int k0 = 0; k0 < 128; k0 += 16) {
#pragma unroll
        for (int i = 0; i < 4; i++) {
            int idx = t + i * 256;
            int r = idx >> 4, c = idx & 15;
            int gr = row0 + r;
            As[c][r] = (gr < N) ? A[(size_t)gr * 128 + k0 + c] : 0.f;
        }
#pragma unroll
        for (int i = 0; i < 4; i++) {
            int idx = t + i * 256;
            int kk = idx >> 6, cc = idx & 63;
            Ws[kk][cc] = (cc < M) ? W[(size_t)(k0 + kk) * M + cc] : 0.f;
        }
        __syncthreads();
#pragma unroll
        for (int kk = 0; kk < 16; kk++) {
            float4 a4 = *(const float4*)&As[kk][ty * 4];
            float4 w4 = *(const float4*)&Ws[kk][tx * 4];
            float a[4] = {a4.x, a4.y, a4.z, a4.w};
            float w[4] = {w4.x, w4.y, w4.z, w4.w};
#pragma unroll
            for (int i = 0; i < 4; i++)
#pragma unroll
                for (int j = 0; j < 4; j++) acc[i][j] += a[i] * w[j];
        }
        __syncthreads();
    }
#pragma unroll
    for (int i = 0; i < 4; i++) {
        int r = row0 + ty * 4 + i;
        if (r >= N) continue;
#pragma unroll
        for (int j = 0; j < 4; j++) {
            int c = tx * 4 + j;
            if (c < M) {
                float o = acc[i][j] + bias[c];
                C[(size_t)r * M + c] = o;
                if (isXl) H0[(size_t)r * M + c] = __float2half_rn(o);
            }
        }
    }
}

// ---------------- fused GATv2 (H=4): warp/node, fp16 gathers ----------------
// Lane l owns channels [4l..4l+3]; 8-lane group = one head; 3-shfl reduce.
__global__ __launch_bounds__(128) void gat4_t(
    const __half* __restrict__ xlh, const float* __restrict__ xr,
    const float* __restrict__ att, const float* __restrict__ bias,
    float* __restrict__ out, int N)
{
    int w = (blockIdx.x * blockDim.x + threadIdx.x) >> 5;
    if (w >= N) return;
    int lane = threadIdx.x & 31;

    const float4 xrv  = *(const float4*)&xr[(size_t)w * 128 + lane * 4];
    const float4 attv = *(const float4*)&att[lane * 4];
    const u64 xr01 = pk2(xrv.x, xrv.y), xr23 = pk2(xrv.z, xrv.w);
    const u64 at01 = pk2(attv.x, attv.y), at23 = pk2(attv.z, attv.w);
    const u64 c02  = pk2(0.2f, 0.2f);

    float mx = -1e30f, den = 0.f;
    u64 acc01 = pk2(0.f, 0.f), acc23 = pk2(0.f, 0.f);

    const int j0 = g_off[w], j1 = g_off[w + 1];
    int s = g_csr[j0];
    uint2 raw = *(const uint2*)&xlh[(size_t)s * 128 + lane * 4];

    for (int j = j0; j < j1; j++) {
        int jn = (j + 1 < j1) ? j + 1 : j;
        int sn = g_csr[jn];
        uint2 rawn = *(const uint2*)&xlh[(size_t)sn * 128 + lane * 4];  // prefetch

        float2 f0 = __half22float2(*(__half2*)&raw.x);
        float2 f1 = __half22float2(*(__half2*)&raw.y);
        u64 v01 = pk2(f0.x, f0.y), v23 = pk2(f1.x, f1.y);

        u64 t01 = fadd2(v01, xr01);
        u64 t23 = fadd2(v23, xr23);
        u64 u01 = fmul2(t01, c02);
        u64 u23 = fmul2(t23, c02);
        float ta, tb, tc, td, ua, ub, uc, ud;
        upk2(t01, ta, tb); upk2(t23, tc, td);
        upk2(u01, ua, ub); upk2(u23, uc, ud);
        ta = fmaxf(ta, ua); tb = fmaxf(tb, ub);
        tc = fmaxf(tc, uc); td = fmaxf(td, ud);

        u64 d2 = fmul2(pk2(ta, tb), at01);
        d2 = ffma2(pk2(tc, td), at23, d2);
        float dl, dh;
        upk2(d2, dl, dh);
        float p = dl + dh;
        p += __shfl_xor_sync(0xffffffffu, p, 1);
        p += __shfl_xor_sync(0xffffffffu, p, 2);
        p += __shfl_xor_sync(0xffffffffu, p, 4);

        float nm = fmaxf(mx, p);
        float sc = __expf(mx - nm);
        float e  = __expf(p - nm);
        mx = nm;
        den = fmaf(den, sc, e);
        u64 sc2 = pk2(sc, sc), e2 = pk2(e, e);
        acc01 = ffma2(acc01, sc2, fmul2(e2, v01));
        acc23 = ffma2(acc23, sc2, fmul2(e2, v23));
        raw = rawn;
    }

    float inv = 1.f / (den + 1e-16f);
    float4 bv = *(const float4*)&bias[lane * 4];
    float a0, a1, a2, a3;
    upk2(acc01, a0, a1); upk2(acc23, a2, a3);
    float4 o;
    o.x = a0 * inv + bv.x; o.x = o.x > 0.f ? o.x : expm1f(o.x);
    o.y = a1 * inv + bv.y; o.y = o.y > 0.f ? o.y : expm1f(o.y);
    o.z = a2 * inv + bv.z; o.z = o.z > 0.f ? o.z : expm1f(o.z);
    o.w = a3 * inv + bv.w; o.w = o.w > 0.f ? o.w : expm1f(o.w);
    *(float4*)&out[(size_t)w * 128 + lane * 4] = o;
}

// ---------------- fused GATv2 (H=1): warp/node, fp16 gathers ----------------
__global__ __launch_bounds__(128) void gat1(
    const __half* __restrict__ xlh, const float* __restrict__ xr,
    const float* __restrict__ att, const float* __restrict__ bias,
    float* __restrict__ out, int N)
{
    int w = (blockIdx.x * blockDim.x + threadIdx.x) >> 5;
    if (w >= N) return;
    int lane = threadIdx.x & 31;

    float xrv  = xr[(size_t)w * 32 + lane];
    float attv = att[lane];
    float mx = -1e30f, den = 0.f, acc = 0.f;

    const int j0 = g_off[w], j1 = g_off[w + 1];
    int s = g_csr[j0];
    float v = __half2float(xlh[(size_t)s * 32 + lane]);

    for (int j = j0; j < j1; j++) {
        int jn = (j + 1 < j1) ? j + 1 : j;
        int sn = g_csr[jn];
        float vn = __half2float(xlh[(size_t)sn * 32 + lane]);

        float t = v + xrv;
        t = fmaxf(t, 0.2f * t);
        float p = warp_sum(t * attv);

        float nm = fmaxf(mx, p);
        float sc = __expf(mx - nm);
        float e  = __expf(p - nm);
        mx = nm;
        den = fmaf(den, sc, e);
        acc = fmaf(acc, sc, e * v);
        v = vn;
    }

    float o = acc / (den + 1e-16f) + bias[lane];
    o = o > 0.f ? o : expm1f(o);
    out[(size_t)w * 32 + lane] = o;
}

// ---------------- fused mean-pool + MLP head: one warp per graph ----------------
__global__ void pool_head(const float* __restrict__ h, const int* __restrict__ batch,
                          const float* __restrict__ meta,
                          const float* __restrict__ Wh1, const float* __restrict__ bh1,
                          const float* __restrict__ Wh2, const float* __restrict__ bh2,
                          float* __restrict__ out, int N, int B, int metaDim)
{
    int g = (blockIdx.x * blockDim.x + threadIdx.x) >> 5;
    int lane = threadIdx.x & 31;
    if (g >= B) return;

    int lo = 0, hi = N;
    while (lo < hi) { int m = (lo + hi) >> 1; if (batch[m] < g) lo = m + 1; else hi = m; }
    int start = lo;
    hi = N;
    while (lo < hi) { int m = (lo + hi) >> 1; if (batch[m] < g + 1) lo = m + 1; else hi = m; }
    int end = lo;

    float sum = 0.f;
    int i = start;
    for (; i + 4 <= end; i += 4) {
        float x0 = h[(size_t)(i + 0) * 32 + lane];
        float x1 = h[(size_t)(i + 1) * 32 + lane];
        float x2 = h[(size_t)(i + 2) * 32 + lane];
        float x3 = h[(size_t)(i + 3) * 32 + lane];
        sum += (x0 + x1) + (x2 + x3);
    }
    for (; i < end; i++) sum += h[(size_t)i * 32 + lane];

    float cnt = fmaxf((float)(end - start), 1.f);
    float emb = sum / cnt;

    float acc = bh1[lane];
#pragma unroll
    for (int k = 0; k < 32; k++)
        acc += __shfl_sync(0xffffffffu, emb, k) * Wh1[k * 32 + lane];
    for (int k = 0; k < metaDim; k++)
        acc += meta[(size_t)g * metaDim + k] * Wh1[(32 + k) * 32 + lane];
    acc = fmaxf(acc, 0.f);
    float p = warp_sum(acc * Wh2[lane]);
    if (lane == 0) out[g] = p + bh2[0];
}

// ---------------- host launcher ----------------
extern "C" void kernel_launch(void* const* d_in, const int* in_sizes, int n_in,
                              void* d_out, int out_size)
{
    const float* x     = (const float*)d_in[0];
    const int*   ei    = (const int*)d_in[1];    // int32 (JAX x64 disabled)
    const int*   batch = (const int*)d_in[2];    // int32
    const float* meta  = (const float*)d_in[3];
    const float* Wl[3]  = {(const float*)d_in[4],  (const float*)d_in[10], (const float*)d_in[16]};
    const float* bl[3]  = {(const float*)d_in[5],  (const float*)d_in[11], (const float*)d_in[17]};
    const float* Wr[3]  = {(const float*)d_in[6],  (const float*)d_in[12], (const float*)d_in[18]};
    const float* br[3]  = {(const float*)d_in[7],  (const float*)d_in[13], (const float*)d_in[19]};
    const float* att[3] = {(const float*)d_in[8],  (const float*)d_in[14], (const float*)d_in[20]};
    const float* bc[3]  = {(const float*)d_in[9],  (const float*)d_in[15], (const float*)d_in[21]};
    const float* Wh1 = (const float*)d_in[22];
    const float* bh1 = (const float*)d_in[23];
    const float* Wh2 = (const float*)d_in[24];
    const float* bh2 = (const float*)d_in[25];

    const int N = in_sizes[0] / 128;
    const int E = in_sizes[1] / 2;
    const int metaDim = 12;
    const int B = in_sizes[3] / metaDim;
    const int Etot = E + N;
    const int nb = (N + 1023) / 1024;

    float *xl, *xr, *hA, *hB;
    __half* xlh;
    int *deg;
    cudaGetSymbolAddress((void**)&xl,  g_xl);
    cudaGetSymbolAddress((void**)&xlh, g_xlh);
    cudaGetSymbolAddress((void**)&xr,  g_xr);
    cudaGetSymbolAddress((void**)&hA,  g_hA);
    cudaGetSymbolAddress((void**)&hB,  g_hB);
    cudaGetSymbolAddress((void**)&deg, g_deg);

    static int smem_set = 0;
    if (!smem_set) {
        cudaFuncSetAttribute(gemm_tc_dual,
                             cudaFuncAttributeMaxDynamicSharedMemorySize,
                             GEMM_SMEM_BYTES);
        smem_set = 1;
    }

    const int warpGrid = (N * 32 + 127) / 128;     // 1 warp / node, 128-thr blocks
    const dim3 bigGrid((N + 127) / 128, 2);
    const dim3 smallGrid((N + 63) / 64, 2);

    // ---- CSR build interleaved with layer-0 GEMM ----
    zero_i<<<(N + 255) / 256, 256>>>(deg, N);
    prep_edges<<<(Etot + 255) / 256, 256>>>(ei, E, N);
    scan_local<<<nb, 1024>>>(N);
    gemm_tc_dual<<<bigGrid, 256, GEMM_SMEM_BYTES>>>(x, Wl[0], bl[0], xl,
                                                       Wr[0], br[0], xr, xlh, N);
    scan_tops<<<1, 64>>>(nb);
    scan_add<<<(N + 255) / 256, 256>>>(N);       // also zeroes g_pos
    scatter_edges<<<(Etot + 255) / 256, 256>>>(ei, E, N);

    // ---- layer 0 (H=4) ----
    gat4_t<<<warpGrid, 128>>>(xlh, xr, att[0], bc[0], hA, N);

    // ---- layer 1 (H=4) ----
    gemm_tc_dual<<<bigGrid, 256, GEMM_SMEM_BYTES>>>(hA, Wl[1], bl[1], xl,
                                                        Wr[1], br[1], xr, xlh, N);
    gat4_t<<<warpGrid, 128>>>(xlh, xr, att[1], bc[1], hB, N);

    // ---- layer 2 (H=1) ----
    gemm128_dual<<<smallGrid, 256>>>(hB, Wl[2], bl[2], xl,
                                         Wr[2], br[2], xr, xlh, N);
    gat1<<<warpGrid, 128>>>(xlh, xr, att[2], bc[2], hA, N);

    // ---- fused mean pool + MLP head ----
    pool_head<<<(B * 32 + 255) / 256, 256>>>(hA, batch, meta, Wh1, bh1, Wh2, bh2,
                                             (float*)d_out, N, B, metaDim);
}